// round 1
// baseline (speedup 1.0000x reference)
#include <cuda_runtime.h>
#include <cuda_bf16.h>
#include <math_constants.h>

#define C_DIM 128
#define D_DEG 64
#define NODE_NUM 8192
#define NEG_SLOPE 0.2f

// Precomputed folded weight vector: v = W_max @ W_score[:128], and
// c0 = dot(b_max, W_score[:128]) + b_score.
__device__ float g_v[C_DIM];
__device__ float g_c0;

__global__ void precompute_kernel(const float* __restrict__ Wmax,
                                  const float* __restrict__ bmax,
                                  const float* __restrict__ Wscore,
                                  const float* __restrict__ bscore) {
    __shared__ float ws1[C_DIM];
    int t = threadIdx.x;  // 128 threads
    ws1[t] = Wscore[t];   // first half of W_score [2C,1]
    __syncthreads();
    const float* row = Wmax + t * C_DIM;
    float acc = 0.f;
#pragma unroll 8
    for (int k = 0; k < C_DIM; k++) acc += row[k] * ws1[k];
    g_v[t] = acc;
    if (t == 0) {
        float c0 = bscore[0];
        for (int k = 0; k < C_DIM; k++) c0 += bmax[k] * ws1[k];
        g_c0 = c0;
    }
}

__global__ __launch_bounds__(256, 4)
void community_kernel(const float* __restrict__ feat,
                      const float* __restrict__ mem,
                      const float* __restrict__ Wscore,
                      const float* __restrict__ Wfit,
                      const float* __restrict__ bfit,
                      const int* __restrict__ neighbors,
                      float* __restrict__ out_cluster,   // [NODE_NUM, C]
                      float* __restrict__ out_scores,    // [NODE_NUM, D]
                      float* __restrict__ out_fit)       // [NODE_NUM]
{
    __shared__ float nbr[D_DEG][C_DIM];   // 32 KB neighbor tile
    __shared__ float w2[C_DIM];           // W_score[128:256]
    __shared__ float wf[C_DIM];           // W_fit
    __shared__ float vsh[C_DIM];          // folded v
    __shared__ int   nid_s[D_DEG];
    __shared__ float part[2][C_DIM];      // half-reduction buffer
    __shared__ float colbuf[C_DIM];       // max_feature / cluster_feature
    __shared__ float sarr[D_DEG];         // per-neighbor scores
    __shared__ float wred[8];
    __shared__ float s_const_sh;

    const int t = threadIdx.x;
    const int node = blockIdx.x;
    const int lane = t & 31;
    const int wid = t >> 5;   // 8 warps

    if (t < C_DIM) {
        w2[t]  = Wscore[C_DIM + t];
        wf[t]  = Wfit[t];
        vsh[t] = g_v[t];
    }
    if (t < D_DEG) nid_s[t] = neighbors[node * D_DEG + t];
    __syncthreads();

    // ---- Gather: nbr[j] = feat[nid] + mem[nid], 8 rows per iteration ----
#pragma unroll
    for (int it = 0; it < 8; it++) {
        int row = it * 8 + wid;
        long long nid = nid_s[row];
        const float4* f4 = reinterpret_cast<const float4*>(feat + nid * C_DIM);
        const float4* m4 = reinterpret_cast<const float4*>(mem  + nid * C_DIM);
        float4 a = f4[lane];
        float4 b = m4[lane];
        float4 r;
        r.x = a.x + b.x; r.y = a.y + b.y; r.z = a.z + b.z; r.w = a.w + b.w;
        reinterpret_cast<float4*>(&nbr[row][0])[lane] = r;
    }
    __syncthreads();

    // ---- Column max over 64 rows (split rows across two thread halves) ----
    const int c = t & 127;
    const int h = t >> 7;
    {
        float m = -CUDART_INF_F;
#pragma unroll 8
        for (int j = h * 32; j < h * 32 + 32; j++) m = fmaxf(m, nbr[j][c]);
        part[h][c] = m;
    }
    __syncthreads();
    if (t < C_DIM) colbuf[t] = fmaxf(part[0][t], part[1][t]);
    __syncthreads();

    // ---- s_const = dot(max_feature, v) + c0  (block reduction) ----
    {
        float p = (t < C_DIM) ? colbuf[t] * vsh[t] : 0.f;
#pragma unroll
        for (int o = 16; o > 0; o >>= 1) p += __shfl_down_sync(0xffffffffu, p, o);
        if (lane == 0) wred[wid] = p;
        __syncthreads();
        if (t == 0) {
            float s = 0.f;
#pragma unroll
            for (int i = 0; i < 8; i++) s += wred[i];
            s_const_sh = s + g_c0;
        }
        __syncthreads();
    }
    const float s_const = s_const_sh;

    // ---- Per-neighbor score: leaky(s_const + dot(nbr_j, w2)) ----
    // Each warp handles 8 rows; one warp-level dot per row.
#pragma unroll
    for (int rr = 0; rr < 8; rr++) {
        int row = wid * 8 + rr;
        float4 a = reinterpret_cast<const float4*>(&nbr[row][0])[lane];
        float4 b = reinterpret_cast<const float4*>(w2)[lane];
        float p = a.x * b.x + a.y * b.y + a.z * b.z + a.w * b.w;
#pragma unroll
        for (int o = 16; o > 0; o >>= 1) p += __shfl_down_sync(0xffffffffu, p, o);
        if (lane == 0) {
            float s = s_const + p;
            sarr[row] = (s >= 0.f) ? s : NEG_SLOPE * s;
        }
    }
    __syncthreads();

    // ---- Segment softmax over 64 scores (warp 0, 2 values per lane) ----
    if (wid == 0) {
        float a0 = sarr[lane], a1 = sarr[lane + 32];
        float mx = fmaxf(a0, a1);
#pragma unroll
        for (int o = 16; o > 0; o >>= 1) mx = fmaxf(mx, __shfl_xor_sync(0xffffffffu, mx, o));
        float e0 = __expf(a0 - mx), e1 = __expf(a1 - mx);
        float sm = e0 + e1;
#pragma unroll
        for (int o = 16; o > 0; o >>= 1) sm += __shfl_xor_sync(0xffffffffu, sm, o);
        float inv = 1.f / sm;
        sarr[lane]      = e0 * inv;
        sarr[lane + 32] = e1 * inv;
    }
    __syncthreads();

    if (t < D_DEG) out_scores[node * D_DEG + t] = sarr[t];

    // ---- Weighted pooling: cluster[c] = sum_j score[j] * nbr[j][c] ----
    {
        float acc = 0.f;
#pragma unroll 8
        for (int j = h * 32; j < h * 32 + 32; j++) acc = fmaf(sarr[j], nbr[j][c], acc);
        part[h][c] = acc;
    }
    __syncthreads();
    if (t < C_DIM) {
        float cf = part[0][t] + part[1][t];
        out_cluster[node * C_DIM + t] = cf;
        colbuf[t] = cf;
    }
    __syncthreads();

    // ---- Fitness: sigmoid(dot(cluster, W_fit) + b_fit) ----
    {
        float p = (t < C_DIM) ? colbuf[t] * wf[t] : 0.f;
#pragma unroll
        for (int o = 16; o > 0; o >>= 1) p += __shfl_down_sync(0xffffffffu, p, o);
        if (lane == 0) wred[wid] = p;
        __syncthreads();
        if (t == 0) {
            float s = 0.f;
#pragma unroll
            for (int i = 0; i < 8; i++) s += wred[i];
            s += bfit[0];
            out_fit[node] = 1.f / (1.f + __expf(-s));
        }
    }
}

extern "C" void kernel_launch(void* const* d_in, const int* in_sizes, int n_in,
                              void* d_out, int out_size) {
    // metadata order:
    // 0 node_features [200000,128] f32
    // 1 memory        [200000,128] f32
    // 2 W_max   [128,128] f32
    // 3 b_max   [128]     f32
    // 4 W_score [256,1]   f32
    // 5 b_score [1]       f32
    // 6 W_fit   [128,1]   f32
    // 7 b_fit   [1]       f32
    // 8 neighbors [524288] i32
    // 9 seg       [524288] i32 (implicit: repeat(arange(8192),64) — unused)
    const float* feat   = (const float*)d_in[0];
    const float* mem    = (const float*)d_in[1];
    const float* Wmax   = (const float*)d_in[2];
    const float* bmax   = (const float*)d_in[3];
    const float* Wscore = (const float*)d_in[4];
    const float* bscore = (const float*)d_in[5];
    const float* Wfit   = (const float*)d_in[6];
    const float* bfit   = (const float*)d_in[7];
    const int*   nbrs   = (const int*)d_in[8];

    float* out = (float*)d_out;
    float* out_cluster = out;                                   // 8192*128
    float* out_scores  = out + NODE_NUM * C_DIM;                // 8192*64
    float* out_fit     = out + NODE_NUM * C_DIM + NODE_NUM * D_DEG;  // 8192

    precompute_kernel<<<1, 128>>>(Wmax, bmax, Wscore, bscore);
    community_kernel<<<NODE_NUM, 256>>>(feat, mem, Wscore, Wfit, bfit, nbrs,
                                        out_cluster, out_scores, out_fit);
}

// round 2
// speedup vs baseline: 1.2387x; 1.2387x over previous
#include <cuda_runtime.h>
#include <cuda_bf16.h>
#include <math_constants.h>

#define C_DIM 128
#define D_DEG 64
#define NODE_NUM 8192
#define NEG_SLOPE 0.2f
#define NWARPS 16          // 512 threads
#define ROWS_PER_WARP 4

// Folded weights: v = W_max @ W_score[:128]; c0 = dot(b_max, W_score[:128]) + b_score
__device__ float g_v[C_DIM];
__device__ float g_c0;

__global__ void precompute_kernel(const float* __restrict__ Wmax,
                                  const float* __restrict__ bmax,
                                  const float* __restrict__ Wscore,
                                  const float* __restrict__ bscore) {
    __shared__ float ws1[C_DIM];
    int t = threadIdx.x;  // 128 threads
    ws1[t] = Wscore[t];
    __syncthreads();
    const float* row = Wmax + t * C_DIM;
    float acc = 0.f;
#pragma unroll 8
    for (int k = 0; k < C_DIM; k++) acc += row[k] * ws1[k];
    g_v[t] = acc;
    if (t == 0) {
        float c0 = bscore[0];
        for (int k = 0; k < C_DIM; k++) c0 += bmax[k] * ws1[k];
        g_c0 = c0;
    }
}

__global__ __launch_bounds__(512)
void community_kernel(const float* __restrict__ feat,
                      const float* __restrict__ mem,
                      const float* __restrict__ Wscore,
                      const float* __restrict__ Wfit,
                      const float* __restrict__ bfit,
                      const int* __restrict__ neighbors,
                      float* __restrict__ out_cluster,   // [NODE_NUM, C]
                      float* __restrict__ out_scores,    // [NODE_NUM, D]
                      float* __restrict__ out_fit)       // [NODE_NUM]
{
    __shared__ int   nid_s[D_DEG];
    __shared__ float part[NWARPS][C_DIM];   // 8KB cross-warp partials
    __shared__ float sraw[D_DEG];           // raw neighbor-dot per row
    __shared__ float sarr[D_DEG];           // softmax scores
    __shared__ float wred[NWARPS];
    __shared__ float s_const_sh;

    const int t    = threadIdx.x;
    const int lane = t & 31;
    const int wid  = t >> 5;   // 0..15
    const int node = blockIdx.x;

    if (t < D_DEG) nid_s[t] = neighbors[node * D_DEG + t];
    __syncthreads();

    // second half of W_score, one float4 per lane (L1-cached across CTAs)
    const float4 w2v = *reinterpret_cast<const float4*>(Wscore + C_DIM + 4 * lane);

    // ---- Gather into registers: warp w owns rows {w, 16+w, 32+w, 48+w} ----
    float4 nb[ROWS_PER_WARP];
#pragma unroll
    for (int i = 0; i < ROWS_PER_WARP; i++) {
        int row = i * NWARPS + wid;
        long long nid = nid_s[row];
        float4 a = reinterpret_cast<const float4*>(feat + nid * C_DIM)[lane];
        float4 b = reinterpret_cast<const float4*>(mem  + nid * C_DIM)[lane];
        nb[i].x = a.x + b.x; nb[i].y = a.y + b.y;
        nb[i].z = a.z + b.z; nb[i].w = a.w + b.w;
    }

    // ---- Fused column-max + per-row score dot (all in registers) ----
    float4 cmax = make_float4(-CUDART_INF_F, -CUDART_INF_F, -CUDART_INF_F, -CUDART_INF_F);
#pragma unroll
    for (int i = 0; i < ROWS_PER_WARP; i++) {
        cmax.x = fmaxf(cmax.x, nb[i].x);
        cmax.y = fmaxf(cmax.y, nb[i].y);
        cmax.z = fmaxf(cmax.z, nb[i].z);
        cmax.w = fmaxf(cmax.w, nb[i].w);
        float p = nb[i].x * w2v.x + nb[i].y * w2v.y + nb[i].z * w2v.z + nb[i].w * w2v.w;
#pragma unroll
        for (int o = 16; o > 0; o >>= 1) p += __shfl_xor_sync(0xffffffffu, p, o);
        if (lane == 0) sraw[i * NWARPS + wid] = p;
    }
    reinterpret_cast<float4*>(&part[wid][0])[lane] = cmax;
    __syncthreads();

    // ---- s_const = dot(colmax, v) + c0 ----
    if (t < C_DIM) {
        float cm = -CUDART_INF_F;
#pragma unroll
        for (int w = 0; w < NWARPS; w++) cm = fmaxf(cm, part[w][t]);
        float p = cm * g_v[t];
#pragma unroll
        for (int o = 16; o > 0; o >>= 1) p += __shfl_xor_sync(0xffffffffu, p, o);
        if (lane == 0) wred[wid] = p;
    }
    __syncthreads();
    if (t == 0) {
        float s = wred[0] + wred[1] + wred[2] + wred[3];
        s_const_sh = s + g_c0;
    }
    __syncthreads();
    const float s_const = s_const_sh;

    // ---- leaky-relu + segment softmax (warp 0, 2 rows per lane) ----
    if (wid == 0) {
        float a0 = s_const + sraw[lane];
        float a1 = s_const + sraw[lane + 32];
        a0 = (a0 >= 0.f) ? a0 : NEG_SLOPE * a0;
        a1 = (a1 >= 0.f) ? a1 : NEG_SLOPE * a1;
        float mx = fmaxf(a0, a1);
#pragma unroll
        for (int o = 16; o > 0; o >>= 1) mx = fmaxf(mx, __shfl_xor_sync(0xffffffffu, mx, o));
        float e0 = __expf(a0 - mx), e1 = __expf(a1 - mx);
        float sm = e0 + e1;
#pragma unroll
        for (int o = 16; o > 0; o >>= 1) sm += __shfl_xor_sync(0xffffffffu, sm, o);
        float inv = 1.f / sm;
        sarr[lane]      = e0 * inv;
        sarr[lane + 32] = e1 * inv;
    }
    __syncthreads();

    if (t < D_DEG) out_scores[node * D_DEG + t] = sarr[t];

    // ---- Weighted pooling from registers ----
    float4 pool = make_float4(0.f, 0.f, 0.f, 0.f);
#pragma unroll
    for (int i = 0; i < ROWS_PER_WARP; i++) {
        float sc = sarr[i * NWARPS + wid];
        pool.x = fmaf(sc, nb[i].x, pool.x);
        pool.y = fmaf(sc, nb[i].y, pool.y);
        pool.z = fmaf(sc, nb[i].z, pool.z);
        pool.w = fmaf(sc, nb[i].w, pool.w);
    }
    reinterpret_cast<float4*>(&part[wid][0])[lane] = pool;
    __syncthreads();

    // ---- Cross-warp sum, write cluster, fused fitness dot ----
    if (t < C_DIM) {
        float cf = 0.f;
#pragma unroll
        for (int w = 0; w < NWARPS; w++) cf += part[w][t];
        out_cluster[node * C_DIM + t] = cf;
        float p = cf * Wfit[t];
#pragma unroll
        for (int o = 16; o > 0; o >>= 1) p += __shfl_xor_sync(0xffffffffu, p, o);
        if (lane == 0) wred[wid] = p;
    }
    __syncthreads();
    if (t == 0) {
        float s = wred[0] + wred[1] + wred[2] + wred[3] + bfit[0];
        out_fit[node] = 1.f / (1.f + __expf(-s));
    }
}

extern "C" void kernel_launch(void* const* d_in, const int* in_sizes, int n_in,
                              void* d_out, int out_size) {
    const float* feat   = (const float*)d_in[0];
    const float* mem    = (const float*)d_in[1];
    const float* Wmax   = (const float*)d_in[2];
    const float* bmax   = (const float*)d_in[3];
    const float* Wscore = (const float*)d_in[4];
    const float* bscore = (const float*)d_in[5];
    const float* Wfit   = (const float*)d_in[6];
    const float* bfit   = (const float*)d_in[7];
    const int*   nbrs   = (const int*)d_in[8];

    float* out = (float*)d_out;
    float* out_cluster = out;                                        // 8192*128
    float* out_scores  = out + NODE_NUM * C_DIM;                     // 8192*64
    float* out_fit     = out + NODE_NUM * C_DIM + NODE_NUM * D_DEG;  // 8192

    precompute_kernel<<<1, 128>>>(Wmax, bmax, Wscore, bscore);
    community_kernel<<<NODE_NUM, 512>>>(feat, mem, Wscore, Wfit, bfit, nbrs,
                                        out_cluster, out_scores, out_fit);
}

// round 3
// speedup vs baseline: 1.2617x; 1.0186x over previous
#include <cuda_runtime.h>
#include <cuda_bf16.h>
#include <math_constants.h>

#define C_DIM 128
#define D_DEG 64
#define NODE_NUM 8192
#define NEG_SLOPE 0.2f
#define NWARPS 16            // 512 threads
#define STRIDE_CTAS 296      // 148 SMs x 2 resident CTAs

// Folded weights: v = W_max @ W_score[:128]; c0 = dot(b_max, W_score[:128]) + b_score
__device__ float g_v[C_DIM];
__device__ float g_c0;

__global__ void precompute_kernel(const float* __restrict__ Wmax,
                                  const float* __restrict__ bmax,
                                  const float* __restrict__ Wscore,
                                  const float* __restrict__ bscore) {
    __shared__ float ws1[C_DIM];
    int t = threadIdx.x;  // 128 threads
    ws1[t] = Wscore[t];
    __syncthreads();
    const float* row = Wmax + t * C_DIM;
    float acc = 0.f;
#pragma unroll 8
    for (int k = 0; k < C_DIM; k++) acc += row[k] * ws1[k];
    g_v[t] = acc;
    if (t == 0) {
        float c0 = bscore[0];
        for (int k = 0; k < C_DIM; k++) c0 += bmax[k] * ws1[k];
        g_c0 = c0;
    }
}

__global__ __launch_bounds__(512, 2)
void community_kernel(const float* __restrict__ feat,
                      const float* __restrict__ mem,
                      const float* __restrict__ Wscore,
                      const float* __restrict__ Wfit,
                      const float* __restrict__ bfit,
                      const int* __restrict__ neighbors,
                      float* __restrict__ out_cluster,   // [NODE_NUM, C]
                      float* __restrict__ out_scores,    // [NODE_NUM, D]
                      float* __restrict__ out_fit)       // [NODE_NUM]
{
    __shared__ float part[NWARPS][C_DIM];   // 8KB cross-warp partials
    __shared__ float sraw[D_DEG];
    __shared__ float sarr[D_DEG];
    __shared__ float wred[NWARPS];
    __shared__ float s_const_sh;

    const int t    = threadIdx.x;
    const int lane = t & 31;
    const int wid  = t >> 5;   // 0..15

    // prefetch mapping: 64 rows x 2 tables x 4 x 128B chunks = 512 threads
    const int pf_row   = t >> 3;
    const int pf_tab   = (t >> 2) & 1;
    const int pf_chunk = t & 3;

    // second half of W_score, one float4 per lane (L1-resident)
    const float4 w2v = *reinterpret_cast<const float4*>(Wscore + C_DIM + 4 * lane);

    for (int node = blockIdx.x; node < NODE_NUM; node += STRIDE_CTAS) {
        // ---- neighbor ids for this node: warp-uniform loads (HW broadcast) ----
        const int* nbase = neighbors + node * D_DEG;
        int nid[4];
#pragma unroll
        for (int i = 0; i < 4; i++) nid[i] = __ldg(nbase + i * NWARPS + wid);

        // ---- issue all 8 gathers up front (batched; L2-hot from prefetch) ----
        float4 af[4], am[4];
#pragma unroll
        for (int i = 0; i < 4; i++)
            af[i] = reinterpret_cast<const float4*>(feat + (long long)nid[i] * C_DIM)[lane];
#pragma unroll
        for (int i = 0; i < 4; i++)
            am[i] = reinterpret_cast<const float4*>(mem + (long long)nid[i] * C_DIM)[lane];

        // ---- prefetch NEXT node's rows into L2 (one 128B line per thread) ----
        {
            int nn = node + STRIDE_CTAS;
            if (nn < NODE_NUM) {
                int pn = __ldg(neighbors + nn * D_DEG + pf_row);
                const float* tb = pf_tab ? mem : feat;
                const char* p = (const char*)(tb + (long long)pn * C_DIM) + pf_chunk * 128;
                asm volatile("prefetch.global.L2 [%0];" :: "l"(p));
            }
        }

        // ---- nbr rows in registers ----
        float4 nb[4];
#pragma unroll
        for (int i = 0; i < 4; i++) {
            nb[i].x = af[i].x + am[i].x; nb[i].y = af[i].y + am[i].y;
            nb[i].z = af[i].z + am[i].z; nb[i].w = af[i].w + am[i].w;
        }

        // ---- fused column-max + per-row score dot ----
        float4 cmax = make_float4(-CUDART_INF_F, -CUDART_INF_F, -CUDART_INF_F, -CUDART_INF_F);
#pragma unroll
        for (int i = 0; i < 4; i++) {
            cmax.x = fmaxf(cmax.x, nb[i].x);
            cmax.y = fmaxf(cmax.y, nb[i].y);
            cmax.z = fmaxf(cmax.z, nb[i].z);
            cmax.w = fmaxf(cmax.w, nb[i].w);
            float p = nb[i].x * w2v.x + nb[i].y * w2v.y + nb[i].z * w2v.z + nb[i].w * w2v.w;
#pragma unroll
            for (int o = 16; o > 0; o >>= 1) p += __shfl_xor_sync(0xffffffffu, p, o);
            if (lane == 0) sraw[i * NWARPS + wid] = p;
        }
        reinterpret_cast<float4*>(&part[wid][0])[lane] = cmax;
        __syncthreads();

        // ---- s_const = dot(colmax, v) + c0 ----
        if (t < C_DIM) {
            float cm = -CUDART_INF_F;
#pragma unroll
            for (int w = 0; w < NWARPS; w++) cm = fmaxf(cm, part[w][t]);
            float p = cm * g_v[t];
#pragma unroll
            for (int o = 16; o > 0; o >>= 1) p += __shfl_xor_sync(0xffffffffu, p, o);
            if (lane == 0) wred[wid] = p;
        }
        __syncthreads();
        if (t == 0) {
            s_const_sh = wred[0] + wred[1] + wred[2] + wred[3] + g_c0;
        }
        __syncthreads();
        const float s_const = s_const_sh;

        // ---- leaky-relu + segment softmax (warp 0) ----
        if (wid == 0) {
            float a0 = s_const + sraw[lane];
            float a1 = s_const + sraw[lane + 32];
            a0 = (a0 >= 0.f) ? a0 : NEG_SLOPE * a0;
            a1 = (a1 >= 0.f) ? a1 : NEG_SLOPE * a1;
            float mx = fmaxf(a0, a1);
#pragma unroll
            for (int o = 16; o > 0; o >>= 1) mx = fmaxf(mx, __shfl_xor_sync(0xffffffffu, mx, o));
            float e0 = __expf(a0 - mx), e1 = __expf(a1 - mx);
            float sm = e0 + e1;
#pragma unroll
            for (int o = 16; o > 0; o >>= 1) sm += __shfl_xor_sync(0xffffffffu, sm, o);
            float inv = 1.f / sm;
            sarr[lane]      = e0 * inv;
            sarr[lane + 32] = e1 * inv;
        }
        __syncthreads();

        if (t < D_DEG) out_scores[node * D_DEG + t] = sarr[t];

        // ---- weighted pooling from registers ----
        float4 pool = make_float4(0.f, 0.f, 0.f, 0.f);
#pragma unroll
        for (int i = 0; i < 4; i++) {
            float sc = sarr[i * NWARPS + wid];
            pool.x = fmaf(sc, nb[i].x, pool.x);
            pool.y = fmaf(sc, nb[i].y, pool.y);
            pool.z = fmaf(sc, nb[i].z, pool.z);
            pool.w = fmaf(sc, nb[i].w, pool.w);
        }
        reinterpret_cast<float4*>(&part[wid][0])[lane] = pool;
        __syncthreads();

        // ---- cross-warp sum, write cluster, fused fitness dot ----
        if (t < C_DIM) {
            float cf = 0.f;
#pragma unroll
            for (int w = 0; w < NWARPS; w++) cf += part[w][t];
            out_cluster[node * C_DIM + t] = cf;
            float p = cf * Wfit[t];
#pragma unroll
            for (int o = 16; o > 0; o >>= 1) p += __shfl_xor_sync(0xffffffffu, p, o);
            if (lane == 0) wred[wid] = p;
        }
        __syncthreads();
        if (t == 0) {
            float s = wred[0] + wred[1] + wred[2] + wred[3] + bfit[0];
            out_fit[node] = 1.f / (1.f + __expf(-s));
        }
        // next iteration's first smem write (part/sraw) is gated behind its own
        // loads + the colmax barrier, which requires t==0 to finish above. Safe.
    }
}

extern "C" void kernel_launch(void* const* d_in, const int* in_sizes, int n_in,
                              void* d_out, int out_size) {
    const float* feat   = (const float*)d_in[0];
    const float* mem    = (const float*)d_in[1];
    const float* Wmax   = (const float*)d_in[2];
    const float* bmax   = (const float*)d_in[3];
    const float* Wscore = (const float*)d_in[4];
    const float* bscore = (const float*)d_in[5];
    const float* Wfit   = (const float*)d_in[6];
    const float* bfit   = (const float*)d_in[7];
    const int*   nbrs   = (const int*)d_in[8];

    float* out = (float*)d_out;
    float* out_cluster = out;                                        // 8192*128
    float* out_scores  = out + NODE_NUM * C_DIM;                     // 8192*64
    float* out_fit     = out + NODE_NUM * C_DIM + NODE_NUM * D_DEG;  // 8192

    precompute_kernel<<<1, 128>>>(Wmax, bmax, Wscore, bscore);
    community_kernel<<<STRIDE_CTAS, 512>>>(feat, mem, Wscore, Wfit, bfit, nbrs,
                                           out_cluster, out_scores, out_fit);
}